// round 7
// baseline (speedup 1.0000x reference)
#include <cuda_runtime.h>
#include <math.h>
#include <stdint.h>

// ---------------- problem constants ----------------
#define BB 4
#define TT 1024
#define EE 768
#define HH 12
#define HD 64
#define LL 4
#define VV 50257
#define MM (BB*TT)          // 4096 rows
#define E3 (3*EE)           // 2304
#define E4 (4*EE)           // 3072
#define LN_EPS 1e-5f
#define L2E 1.4426950408889634f

// ---------------- scratch (static device allocations; no cudaMalloc) ----------------
__device__ __align__(256) float g_x   [(size_t)MM*EE];
__device__ __align__(256) float g_xn  [(size_t)MM*EE];
__device__ __align__(256) float g_qkv [(size_t)MM*E3];
__device__ __align__(256) float g_y   [(size_t)MM*EE];
__device__ __align__(256) float g_h1  [(size_t)MM*E4];
__device__ __align__(256) float g_nll [MM];
__device__ __align__(256) float g_logits_fb[(size_t)MM*VV];   // fallback logits store

// ---------------- embedding ----------------
__global__ void embed_kernel(const int* __restrict__ idx,
                             const float* __restrict__ wte,
                             const float* __restrict__ wpe,
                             float* __restrict__ X)
{
    int i = blockIdx.x * 256 + threadIdx.x;
    if (i >= MM * EE) return;
    int m = i / EE;
    int e = i - m * EE;
    int tok = idx[m];
    X[i] = wte[(size_t)tok * EE + e] + wpe[(size_t)(m & (TT - 1)) * EE + e];
}

// ---------------- layernorm (one block per row, 256 threads, E=768) ----------------
__global__ void ln_kernel(const float* __restrict__ X,
                          const float* __restrict__ w,
                          const float* __restrict__ b,
                          float* __restrict__ O)
{
    int row = blockIdx.x;
    int t   = threadIdx.x;
    const float* xr = X + (size_t)row * EE;
    float v0 = xr[t], v1 = xr[t + 256], v2 = xr[t + 512];
    float s  = v0 + v1 + v2;
    float ss = v0 * v0 + v1 * v1 + v2 * v2;
    #pragma unroll
    for (int o = 16; o > 0; o >>= 1) {
        s  += __shfl_xor_sync(0xffffffffu, s, o);
        ss += __shfl_xor_sync(0xffffffffu, ss, o);
    }
    __shared__ float rs[8], rss[8];
    int wid = t >> 5, lid = t & 31;
    if (lid == 0) { rs[wid] = s; rss[wid] = ss; }
    __syncthreads();
    s = 0.f; ss = 0.f;
    #pragma unroll
    for (int i = 0; i < 8; i++) { s += rs[i]; ss += rss[i]; }
    float mean = s * (1.0f / EE);
    float var  = ss * (1.0f / EE) - mean * mean;
    float inv  = rsqrtf(var + LN_EPS);
    float* orow = O + (size_t)row * EE;
    orow[t]       = (v0 - mean) * inv * w[t]       + b[t];
    orow[t + 256] = (v1 - mean) * inv * w[t + 256] + b[t + 256];
    orow[t + 512] = (v2 - mean) * inv * w[t + 512] + b[t + 512];
}

// ---------------- packed f32x2 helpers ----------------
__device__ __forceinline__ unsigned long long pack_dup(float a) {
    unsigned long long r;
    unsigned int u = __float_as_uint(a);
    asm("mov.b64 %0, {%1, %1};" : "=l"(r) : "r"(u));
    return r;
}
__device__ __forceinline__ void fma2(unsigned long long& c,
                                     unsigned long long a,
                                     unsigned long long b) {
    asm("fma.rn.f32x2 %0, %1, %2, %0;" : "+l"(c) : "l"(a), "l"(b));
}

// ---------------- SGEMM: C[M,N] = A[M,K] @ W[N,K]^T (+bias)(+res)(+gelu) ----------------
// epi: 0 = plain(+bias if bias!=null), 2 = +residual, 3 = +gelu
// Inner loop uses packed fma.rn.f32x2 (FFMA2): 32 packed FMAs + 8 dup-packs
// per k-step instead of 64 FFMA — 2x fma-pipe throughput, IEEE fp32 per lane.
// Vectorized epilogue only when N % 4 == 0 (odd N = V would misalign float4).
__global__ __launch_bounds__(256, 2)
void sgemm_nt(const float* __restrict__ A, const float* __restrict__ W,
              const float* __restrict__ bias, const float* __restrict__ res,
              float* __restrict__ C, int M, int N, int K, int epi)
{
    __shared__ __align__(16) float As[2][8][132];
    __shared__ __align__(16) float Bs[2][8][132];

    const int t  = threadIdx.x;
    const int bm = blockIdx.y * 128;
    const int bn = blockIdx.x * 128;
    const int lr = t >> 1;
    const int lc = (t & 1) * 4;
    const int tx = t & 15;
    const int ty = t >> 4;

    const float* Aptr = A + (size_t)(bm + lr) * K + lc;
    const int    wrow = bn + lr;
    const float* Wptr = W + (size_t)wrow * K + lc;
    const bool   wok  = (wrow < N);

    float4 ra = *(const float4*)Aptr;
    float4 rb = wok ? *(const float4*)Wptr : make_float4(0.f, 0.f, 0.f, 0.f);

    unsigned long long c2[8][4];
    #pragma unroll
    for (int i = 0; i < 8; i++)
        #pragma unroll
        for (int jp = 0; jp < 4; jp++) c2[i][jp] = 0ull;

    int buf = 0;
    As[0][lc + 0][lr] = ra.x; As[0][lc + 1][lr] = ra.y;
    As[0][lc + 2][lr] = ra.z; As[0][lc + 3][lr] = ra.w;
    Bs[0][lc + 0][lr] = rb.x; Bs[0][lc + 1][lr] = rb.y;
    Bs[0][lc + 2][lr] = rb.z; Bs[0][lc + 3][lr] = rb.w;
    __syncthreads();

    union F4U2 { float4 f; unsigned long long u[2]; };

    for (int kk = 0; kk < K; kk += 8) {
        bool more = (kk + 8) < K;
        if (more) {
            ra = *(const float4*)(Aptr + kk + 8);
            rb = wok ? *(const float4*)(Wptr + kk + 8) : make_float4(0.f, 0.f, 0.f, 0.f);
        }
        #pragma unroll
        for (int k = 0; k < 8; k++) {
            float4 a0 = *(const float4*)&As[buf][k][ty * 4];
            float4 a1 = *(const float4*)&As[buf][k][64 + ty * 4];
            F4U2 b0, b1;
            b0.f = *(const float4*)&Bs[buf][k][tx * 4];
            b1.f = *(const float4*)&Bs[buf][k][64 + tx * 4];
            unsigned long long bp[4] = {b0.u[0], b0.u[1], b1.u[0], b1.u[1]};
            unsigned long long ap[8];
            ap[0] = pack_dup(a0.x); ap[1] = pack_dup(a0.y);
            ap[2] = pack_dup(a0.z); ap[3] = pack_dup(a0.w);
            ap[4] = pack_dup(a1.x); ap[5] = pack_dup(a1.y);
            ap[6] = pack_dup(a1.z); ap[7] = pack_dup(a1.w);
            #pragma unroll
            for (int i = 0; i < 8; i++)
                #pragma unroll
                for (int jp = 0; jp < 4; jp++)
                    fma2(c2[i][jp], ap[i], bp[jp]);
        }
        if (more) {
            int nb = buf ^ 1;
            As[nb][lc + 0][lr] = ra.x; As[nb][lc + 1][lr] = ra.y;
            As[nb][lc + 2][lr] = ra.z; As[nb][lc + 3][lr] = ra.w;
            Bs[nb][lc + 0][lr] = rb.x; Bs[nb][lc + 1][lr] = rb.y;
            Bs[nb][lc + 2][lr] = rb.z; Bs[nb][lc + 3][lr] = rb.w;
            __syncthreads();
            buf = nb;
        }
    }

    // unpack packed accumulators
    float c[8][8];
    #pragma unroll
    for (int i = 0; i < 8; i++)
        #pragma unroll
        for (int jp = 0; jp < 4; jp++) {
            unsigned int lo, hi;
            asm("mov.b64 {%0, %1}, %2;" : "=r"(lo), "=r"(hi) : "l"(c2[i][jp]));
            c[i][2 * jp]     = __uint_as_float(lo);
            c[i][2 * jp + 1] = __uint_as_float(hi);
        }

    const bool vec_ok = ((N & 3) == 0);

    #pragma unroll
    for (int gi = 0; gi < 2; gi++) {
        #pragma unroll
        for (int i = 0; i < 4; i++) {
            int row = bm + gi * 64 + ty * 4 + i;
            float* Crow = C + (size_t)row * N;
            const float* Rrow = res + (size_t)row * N;  // only deref if epi==2
            #pragma unroll
            for (int gj = 0; gj < 2; gj++) {
                int col = bn + gj * 64 + tx * 4;
                float v[4] = {c[gi * 4 + i][gj * 4 + 0], c[gi * 4 + i][gj * 4 + 1],
                              c[gi * 4 + i][gj * 4 + 2], c[gi * 4 + i][gj * 4 + 3]};
                if (vec_ok && col + 3 < N) {
                    if (bias) {
                        float4 bb = *(const float4*)(bias + col);
                        v[0] += bb.x; v[1] += bb.y; v[2] += bb.z; v[3] += bb.w;
                    }
                    if (epi == 2) {
                        float4 rr = *(const float4*)(Rrow + col);
                        v[0] += rr.x; v[1] += rr.y; v[2] += rr.z; v[3] += rr.w;
                    } else if (epi == 3) {
                        #pragma unroll
                        for (int u = 0; u < 4; u++)
                            v[u] = 0.5f * v[u] * (1.0f + erff(v[u] * 0.70710678118654752f));
                    }
                    *(float4*)(Crow + col) = make_float4(v[0], v[1], v[2], v[3]);
                } else {
                    #pragma unroll
                    for (int u = 0; u < 4; u++) {
                        if (col + u < N) {
                            float vv = v[u];
                            if (bias) vv += bias[col + u];
                            if (epi == 2) vv += Rrow[col + u];
                            else if (epi == 3) vv = 0.5f * vv * (1.0f + erff(vv * 0.70710678118654752f));
                            Crow[col + u] = vv;
                        }
                    }
                }
            }
        }
    }
}

// ---------------- causal attention (flash-style, 1 thread = 1 query row) -----------
__global__ __launch_bounds__(128)
void attn_kernel(const float* __restrict__ qkv, float* __restrict__ Y)
{
    int qt = blockIdx.x, h = blockIdx.y, b = blockIdx.z;
    int tid = threadIdx.x;
    int qi  = qt * 128 + tid;

    const float* base = qkv + (size_t)b * TT * E3;
    const float* qp   = base + (size_t)qi * E3 + h * HD;

    float q[HD], acc[HD];
    #pragma unroll
    for (int d = 0; d < HD; d += 4) {
        float4 u = *(const float4*)(qp + d);
        q[d] = u.x; q[d+1] = u.y; q[d+2] = u.z; q[d+3] = u.w;
        acc[d] = acc[d+1] = acc[d+2] = acc[d+3] = 0.f;
    }
    float mx = -INFINITY, l = 0.f;

    __shared__ __align__(16) float Ks[32][HD];
    __shared__ __align__(16) float Vs[32][HD];

    const float* kbase = base + EE     + h * HD;
    const float* vbase = base + 2 * EE + h * HD;
    int nkt = (qt + 1) * 4;   // tiles of 32 keys covering [0, qt*128+128)

    for (int kt = 0; kt < nkt; kt++) {
        int j0 = kt * 32;
        __syncthreads();
        #pragma unroll
        for (int w = 0; w < 4; w++) {
            int p4 = tid + w * 128;       // float4 index, 0..511
            int j  = p4 >> 4;
            int dc = (p4 & 15) * 4;
            *(float4*)&Ks[j][dc] = *(const float4*)(kbase + (size_t)(j0 + j) * E3 + dc);
            *(float4*)&Vs[j][dc] = *(const float4*)(vbase + (size_t)(j0 + j) * E3 + dc);
        }
        __syncthreads();

        #pragma unroll
        for (int half = 0; half < 2; half++) {
            int jb = half * 16;
            float s[16];
            #pragma unroll
            for (int j = 0; j < 16; j++) {
                float sum = 0.f;
                #pragma unroll
                for (int d = 0; d < HD; d += 4) {
                    float4 kv = *(const float4*)&Ks[jb + j][d];
                    sum += q[d] * kv.x + q[d+1] * kv.y + q[d+2] * kv.z + q[d+3] * kv.w;
                }
                s[j] = (j0 + jb + j <= qi) ? sum * 0.125f : -INFINITY;
            }
            float tmax = s[0];
            #pragma unroll
            for (int j = 1; j < 16; j++) tmax = fmaxf(tmax, s[j]);
            float nm   = fmaxf(mx, tmax);
            float corr = exp2f((mx - nm) * L2E);
            l *= corr;
            #pragma unroll
            for (int d = 0; d < HD; d++) acc[d] *= corr;
            #pragma unroll
            for (int j = 0; j < 16; j++) {
                float p = exp2f((s[j] - nm) * L2E);
                l += p;
                #pragma unroll
                for (int d = 0; d < HD; d += 4) {
                    float4 vv = *(const float4*)&Vs[jb + j][d];
                    acc[d]   += p * vv.x; acc[d+1] += p * vv.y;
                    acc[d+2] += p * vv.z; acc[d+3] += p * vv.w;
                }
            }
            mx = nm;
        }
    }
    float inv = 1.0f / l;
    float* yp = Y + (size_t)(b * TT + qi) * EE + h * HD;
    #pragma unroll
    for (int d = 0; d < HD; d += 4)
        *(float4*)(yp + d) = make_float4(acc[d] * inv, acc[d+1] * inv,
                                         acc[d+2] * inv, acc[d+3] * inv);
}

// ---------------- loss: per-row online logsumexp ----------------
__global__ void loss_row_kernel(const float* __restrict__ logits,
                                const int* __restrict__ tgt,
                                float* __restrict__ nll)
{
    int row = blockIdx.x;
    int t   = threadIdx.x;
    const float* Lr = logits + (size_t)row * VV;
    float mx = -INFINITY, s = 0.f;
    for (int j = t; j < VV; j += 256) {
        float x  = Lr[j];
        float nm = fmaxf(mx, x);
        s = s * exp2f((mx - nm) * L2E) + exp2f((x - nm) * L2E);
        mx = nm;
    }
    #pragma unroll
    for (int o = 16; o > 0; o >>= 1) {
        float om = __shfl_xor_sync(0xffffffffu, mx, o);
        float os = __shfl_xor_sync(0xffffffffu, s, o);
        float nm = fmaxf(mx, om);
        s = s * exp2f((mx - nm) * L2E) + os * exp2f((om - nm) * L2E);
        mx = nm;
    }
    __shared__ float sm[8], ssum[8];
    int wid = t >> 5, lid = t & 31;
    if (lid == 0) { sm[wid] = mx; ssum[wid] = s; }
    __syncthreads();
    if (t == 0) {
        float M = sm[0], S = ssum[0];
        #pragma unroll
        for (int i = 1; i < 8; i++) {
            float nm = fmaxf(M, sm[i]);
            S = S * exp2f((M - nm) * L2E) + ssum[i] * exp2f((sm[i] - nm) * L2E);
            M = nm;
        }
        int tg = tgt[row];
        nll[row] = (tg != -1) ? (M + logf(S)) - Lr[tg] : 0.f;
    }
}

__global__ void loss_final_kernel(const float* __restrict__ nll,
                                  const int* __restrict__ tgt,
                                  float* __restrict__ out)
{
    int t = threadIdx.x;
    float s = 0.f; int c = 0;
    for (int i = t; i < MM; i += 256) {
        if (tgt[i] != -1) { s += nll[i]; c++; }
    }
    #pragma unroll
    for (int o = 16; o > 0; o >>= 1) {
        s += __shfl_xor_sync(0xffffffffu, s, o);
        c += __shfl_xor_sync(0xffffffffu, c, o);
    }
    __shared__ float rs[8]; __shared__ int rc[8];
    int wid = t >> 5, lid = t & 31;
    if (lid == 0) { rs[wid] = s; rc[wid] = c; }
    __syncthreads();
    if (t == 0) {
        float S = 0.f; int C = 0;
        #pragma unroll
        for (int i = 0; i < 8; i++) { S += rs[i]; C += rc[i]; }
        out[0] = S / fmaxf((float)C, 1.f);
    }
}

// ---------------- launcher ----------------
extern "C" void kernel_launch(void* const* d_in, const int* in_sizes, int n_in,
                              void* d_out, int out_size)
{
    const int*   idx        = (const int*)  d_in[0];
    const int*   tgt        = (const int*)  d_in[1];
    const float* wte        = (const float*)d_in[2];
    const float* wpe        = (const float*)d_in[3];
    const float* ln1_w      = (const float*)d_in[4];
    const float* ln1_b      = (const float*)d_in[5];
    const float* attn_w     = (const float*)d_in[6];
    const float* attn_b     = (const float*)d_in[7];
    const float* attnproj_w = (const float*)d_in[8];
    const float* attnproj_b = (const float*)d_in[9];
    const float* ln2_w      = (const float*)d_in[10];
    const float* ln2_b      = (const float*)d_in[11];
    const float* fc_w       = (const float*)d_in[12];
    const float* fc_b       = (const float*)d_in[13];
    const float* proj_w     = (const float*)d_in[14];
    const float* proj_b     = (const float*)d_in[15];
    const float* lnf_w      = (const float*)d_in[16];
    const float* lnf_b      = (const float*)d_in[17];

    float *x, *xn, *qkv, *y, *h1, *nll, *lfb;
    cudaGetSymbolAddress((void**)&x,   g_x);
    cudaGetSymbolAddress((void**)&xn,  g_xn);
    cudaGetSymbolAddress((void**)&qkv, g_qkv);
    cudaGetSymbolAddress((void**)&y,   g_y);
    cudaGetSymbolAddress((void**)&h1,  g_h1);
    cudaGetSymbolAddress((void**)&nll, g_nll);
    cudaGetSymbolAddress((void**)&lfb, g_logits_fb);

    const long long BTV = (long long)MM * VV;
    float* logits = lfb;
    float* lossp  = nullptr;
    if ((long long)out_size == BTV + 1) { logits = (float*)d_out; lossp = (float*)d_out + BTV; }
    else if ((long long)out_size == BTV) { logits = (float*)d_out; }
    else { logits = lfb; lossp = (float*)d_out + (out_size - 1); }

    // embedding
    embed_kernel<<<(MM * EE + 255) / 256, 256>>>(idx, wte, wpe, x);

    for (int l = 0; l < LL; l++) {
        // --- attention block ---
        ln_kernel<<<MM, 256>>>(x, ln1_w + l * EE, ln1_b + l * EE, xn);
        sgemm_nt<<<dim3(E3 / 128, MM / 128), 256>>>(
            xn, attn_w + (size_t)l * E3 * EE, attn_b + (size_t)l * E3,
            nullptr, qkv, MM, E3, EE, 0);
        attn_kernel<<<dim3(TT / 128, HH, BB), 128>>>(qkv, y);
        sgemm_nt<<<dim3(EE / 128, MM / 128), 256>>>(
            y, attnproj_w + (size_t)l * EE * EE, attnproj_b + (size_t)l * EE,
            x, x, MM, EE, EE, 2);
        // --- mlp block ---
        ln_kernel<<<MM, 256>>>(x, ln2_w + l * EE, ln2_b + l * EE, xn);
        sgemm_nt<<<dim3(E4 / 128, MM / 128), 256>>>(
            xn, fc_w + (size_t)l * E4 * EE, fc_b + (size_t)l * E4,
            nullptr, h1, MM, E4, EE, 3);
        sgemm_nt<<<dim3(EE / 128, MM / 128), 256>>>(
            h1, proj_w + (size_t)l * EE * E4, proj_b + (size_t)l * EE,
            x, x, MM, EE, E4, 2);
    }

    // final LN + lm_head (tied wte)
    ln_kernel<<<MM, 256>>>(x, lnf_w, lnf_b, xn);
    sgemm_nt<<<dim3((VV + 127) / 128, MM / 128), 256>>>(
        xn, wte, nullptr, nullptr, logits, MM, VV, EE, 0);

    if (lossp) {
        loss_row_kernel<<<MM, 256>>>(logits, tgt, nll);
        loss_final_kernel<<<1, 256>>>(nll, tgt, lossp);
    }
}

// round 12
// speedup vs baseline: 1.8356x; 1.8356x over previous
#include <cuda_runtime.h>
#include <cuda_bf16.h>
#include <math.h>
#include <stdint.h>

// ---------------- problem constants ----------------
#define BB 4
#define TT 1024
#define EE 768
#define HH 12
#define HD 64
#define LL 4
#define VV 50257
#define MM (BB*TT)          // 4096 rows
#define E3 (3*EE)           // 2304
#define E4 (4*EE)           // 3072
#define LN_EPS 1e-5f
#define L2E 1.4426950408889634f

// ---------------- scratch (static device allocations; no cudaMalloc) ----------------
__device__ __align__(256) float g_x   [(size_t)MM*EE];
__device__ __align__(256) float g_xn  [(size_t)MM*EE];
__device__ __align__(256) float g_qkv [(size_t)MM*E3];
__device__ __align__(256) float g_y   [(size_t)MM*EE];
__device__ __align__(256) float g_h1  [(size_t)MM*E4];
__device__ __align__(256) float g_nll [MM];
__device__ __align__(256) float g_logits_fb[(size_t)MM*VV];        // fallback logits
__device__ __align__(256) __nv_bfloat16 g_asp[(size_t)MM*3*E4];    // split A (max K=3072)
__device__ __align__(256) __nv_bfloat16 g_wsp[(size_t)VV*3*EE];    // split W (max V x 3*768)

// ---------------- small ptx helpers ----------------
__device__ __forceinline__ uint32_t smem_to_u32(const void* p) {
    uint32_t a;
    asm("{ .reg .u64 t; cvta.to.shared.u64 t, %1; cvt.u32.u64 %0, t; }" : "=r"(a) : "l"(p));
    return a;
}
__device__ __forceinline__ void cp_async16(uint32_t dst, const void* src, int src_sz) {
    asm volatile("cp.async.cg.shared.global [%0], [%1], 16, %2;"
                 :: "r"(dst), "l"(src), "r"(src_sz) : "memory");
}
#define CPASYNC_COMMIT() asm volatile("cp.async.commit_group;" ::: "memory")
#define CPASYNC_WAIT2()  asm volatile("cp.async.wait_group 2;"  ::: "memory")

__device__ __forceinline__ void ldsm_x4(uint32_t* r, uint32_t addr) {
    asm volatile("ldmatrix.sync.aligned.m8n8.x4.shared.b16 {%0,%1,%2,%3}, [%4];"
                 : "=r"(r[0]), "=r"(r[1]), "=r"(r[2]), "=r"(r[3]) : "r"(addr));
}
__device__ __forceinline__ void ldsm_x2(uint32_t* r, uint32_t addr) {
    asm volatile("ldmatrix.sync.aligned.m8n8.x2.shared.b16 {%0,%1}, [%2];"
                 : "=r"(r[0]), "=r"(r[1]) : "r"(addr));
}
__device__ __forceinline__ void mma16816(float* c, const uint32_t* a, const uint32_t* b) {
    asm volatile(
        "mma.sync.aligned.m16n8k16.row.col.f32.bf16.bf16.f32 "
        "{%0,%1,%2,%3}, {%4,%5,%6,%7}, {%8,%9}, {%0,%1,%2,%3};"
        : "+f"(c[0]), "+f"(c[1]), "+f"(c[2]), "+f"(c[3])
        : "r"(a[0]), "r"(a[1]), "r"(a[2]), "r"(a[3]), "r"(b[0]), "r"(b[1]));
}

// ---------------- split conversion: fp32 -> bf16 (hi,lo) planes ----------------
__device__ __forceinline__ unsigned short bf_bits(__nv_bfloat16 h) {
    return *reinterpret_cast<unsigned short*>(&h);
}

// A' rows: [hi(K) | hi(K) | lo(K)]
__global__ void split_a4(const float* __restrict__ src, __nv_bfloat16* __restrict__ dst,
                         int total4, int K)
{
    int i = blockIdx.x * 256 + threadIdx.x;
    if (i >= total4) return;
    int K4 = K >> 2;
    int r = i / K4, k4 = i - r * K4;
    float4 x = ((const float4*)src)[i];
    __nv_bfloat16 h0 = __float2bfloat16(x.x), h1 = __float2bfloat16(x.y);
    __nv_bfloat16 h2 = __float2bfloat16(x.z), h3 = __float2bfloat16(x.w);
    __nv_bfloat16 l0 = __float2bfloat16(x.x - __bfloat162float(h0));
    __nv_bfloat16 l1 = __float2bfloat16(x.y - __bfloat162float(h1));
    __nv_bfloat16 l2 = __float2bfloat16(x.z - __bfloat162float(h2));
    __nv_bfloat16 l3 = __float2bfloat16(x.w - __bfloat162float(h3));
    ushort4 hv = make_ushort4(bf_bits(h0), bf_bits(h1), bf_bits(h2), bf_bits(h3));
    ushort4 lv = make_ushort4(bf_bits(l0), bf_bits(l1), bf_bits(l2), bf_bits(l3));
    size_t base = (size_t)r * (3 * K) + k4 * 4;
    *(ushort4*)(dst + base)         = hv;
    *(ushort4*)(dst + base + K)     = hv;
    *(ushort4*)(dst + base + 2 * K) = lv;
}

// W' rows: [hi(K) | lo(K) | hi(K)]
__global__ void split_w4(const float* __restrict__ src, __nv_bfloat16* __restrict__ dst,
                         int total4, int K)
{
    int i = blockIdx.x * 256 + threadIdx.x;
    if (i >= total4) return;
    int K4 = K >> 2;
    int r = i / K4, k4 = i - r * K4;
    float4 x = ((const float4*)src)[i];
    __nv_bfloat16 h0 = __float2bfloat16(x.x), h1 = __float2bfloat16(x.y);
    __nv_bfloat16 h2 = __float2bfloat16(x.z), h3 = __float2bfloat16(x.w);
    __nv_bfloat16 l0 = __float2bfloat16(x.x - __bfloat162float(h0));
    __nv_bfloat16 l1 = __float2bfloat16(x.y - __bfloat162float(h1));
    __nv_bfloat16 l2 = __float2bfloat16(x.z - __bfloat162float(h2));
    __nv_bfloat16 l3 = __float2bfloat16(x.w - __bfloat162float(h3));
    ushort4 hv = make_ushort4(bf_bits(h0), bf_bits(h1), bf_bits(h2), bf_bits(h3));
    ushort4 lv = make_ushort4(bf_bits(l0), bf_bits(l1), bf_bits(l2), bf_bits(l3));
    size_t base = (size_t)r * (3 * K) + k4 * 4;
    *(ushort4*)(dst + base)         = hv;
    *(ushort4*)(dst + base + K)     = lv;
    *(ushort4*)(dst + base + 2 * K) = hv;
}

// ---------------- HMMA GEMM: C[M,N] = A'[M,K3] @ W'[N,K3]^T (+bias)(+res)(+gelu) ----
// 128x128 CTA tile, 8 warps (2x4), warp tile 64x32, K stage = 32 elements,
// 4-stage cp.async pipeline. Smem rows padded to 40 bf16 (80B) -> ldmatrix
// row-stride 80B covers all 32 banks (20r mod 32 distinct for r=0..7).
// epi: 0 plain(+bias), 2 +residual, 3 +gelu.
#define ROWB   80            // padded row bytes (32 bf16 data + 8 pad)
#define STAGEB (128 * ROWB)  // 10240 B per operand stage
#define NSTAGE 4
#define GM_SMEM (2 * NSTAGE * STAGEB)   // 81920 B

__global__ void __launch_bounds__(256, 2)
gemm_mma(const __nv_bfloat16* __restrict__ A, const __nv_bfloat16* __restrict__ W,
         const float* __restrict__ bias, const float* __restrict__ res,
         float* __restrict__ C, int M, int N, int K3, int epi)
{
    extern __shared__ char smem[];
    const uint32_t sbase = smem_to_u32(smem);
    const uint32_t sB0 = sbase + NSTAGE * STAGEB;
    const int tid  = threadIdx.x;
    const int lane = tid & 31;
    const int warp = tid >> 5;
    const int wm = warp & 1;          // 2 m-blocks of 64
    const int wn = warp >> 1;         // 4 n-blocks of 32
    const int bm = blockIdx.x * 128;
    const int bn = blockIdx.y * 128;

    const size_t strB = (size_t)K3 * 2;   // row stride bytes
    const int NC = K3 >> 5;               // stages of K=32

    const char* Abase = (const char*)A + (size_t)bm * strB;
    const char* Wbase = (const char*)W + (size_t)bn * strB;

    float acc[4][4][4];
    #pragma unroll
    for (int mt = 0; mt < 4; mt++)
        #pragma unroll
        for (int nt = 0; nt < 4; nt++)
            #pragma unroll
            for (int e = 0; e < 4; e++) acc[mt][nt][e] = 0.f;

    // per-thread load slots: idx = p*256+tid -> row = idx/4, 16B chunk = idx%4
    const int r0 = tid >> 2, c0 = (tid & 3) * 16;
    const int r1 = r0 + 64;

    auto load_stage = [&](int s) {
        const int buf = s & (NSTAGE - 1);
        const uint32_t sa = sbase + buf * STAGEB;
        const uint32_t sb = sB0   + buf * STAGEB;
        const size_t kof = (size_t)s * 64;   // 32 elems * 2B
        // A rows always valid (M multiple of 128)
        cp_async16(sa + r0 * ROWB + c0, Abase + (size_t)r0 * strB + kof + c0, 16);
        cp_async16(sa + r1 * ROWB + c0, Abase + (size_t)r1 * strB + kof + c0, 16);
        int v0 = (bn + r0 < N) ? 16 : 0;
        int v1 = (bn + r1 < N) ? 16 : 0;
        const char* w0 = Wbase + (v0 ? (size_t)r0 * strB : 0) + kof + c0;
        const char* w1 = Wbase + (v1 ? (size_t)r1 * strB : 0) + kof + c0;
        cp_async16(sb + r0 * ROWB + c0, w0, v0);
        cp_async16(sb + r1 * ROWB + c0, w1, v1);
    };

    auto compute_stage = [&](int buf) {
        const uint32_t sa = sbase + buf * STAGEB + (wm * 64) * ROWB;
        const uint32_t sb = sB0   + buf * STAGEB + (wn * 32) * ROWB;
        const uint32_t arow = (lane & 15) * ROWB + ((lane >> 4) << 4);
        const uint32_t brow = (lane & 7)  * ROWB + (((lane >> 3) & 1) << 4);
        #pragma unroll
        for (int ks = 0; ks < 2; ks++) {
            const uint32_t kof = ks * 32;   // 16 elems * 2B
            uint32_t a[4][4], b[4][2];
            #pragma unroll
            for (int mt = 0; mt < 4; mt++)
                ldsm_x4(a[mt], sa + mt * 16 * ROWB + arow + kof);
            #pragma unroll
            for (int nt = 0; nt < 4; nt++)
                ldsm_x2(b[nt], sb + nt * 8 * ROWB + brow + kof);
            #pragma unroll
            for (int mt = 0; mt < 4; mt++)
                #pragma unroll
                for (int nt = 0; nt < 4; nt++)
                    mma16816(acc[mt][nt], a[mt], b[nt]);
        }
    };

    // prologue: stages 0..2
    #pragma unroll
    for (int s = 0; s < NSTAGE - 1; s++) {
        if (s < NC) load_stage(s);
        CPASYNC_COMMIT();
    }
    for (int i = 0; i < NC; i++) {
        CPASYNC_WAIT2();
        __syncthreads();
        compute_stage(i & (NSTAGE - 1));
        __syncthreads();
        if (i + NSTAGE - 1 < NC) load_stage(i + NSTAGE - 1);
        CPASYNC_COMMIT();
    }

    // ---- epilogue: fragment -> gmem with fused bias/res/gelu ----
    const int g = lane >> 2, q = lane & 3;
    #pragma unroll
    for (int mt = 0; mt < 4; mt++) {
        #pragma unroll
        for (int nt = 0; nt < 4; nt++) {
            int row = bm + wm * 64 + mt * 16 + g;
            int col = bn + wn * 32 + nt * 8 + 2 * q;
            #pragma unroll
            for (int half = 0; half < 2; half++) {       // rows g, g+8
                int rr = row + half * 8;
                float* Crow = C + (size_t)rr * N;
                const float* Rrow = res + (size_t)rr * N;
                #pragma unroll
                for (int e = 0; e < 2; e++) {            // cols col, col+1
                    int cc = col + e;
                    if (cc >= N) continue;
                    float v = acc[mt][nt][half * 2 + e];
                    if (bias) v += bias[cc];
                    if (epi == 2)      v += Rrow[cc];
                    else if (epi == 3) v = 0.5f * v * (1.0f + erff(v * 0.70710678118654752f));
                    Crow[cc] = v;
                }
            }
        }
    }
}

// ---------------- embedding ----------------
__global__ void embed_kernel(const int* __restrict__ idx,
                             const float* __restrict__ wte,
                             const float* __restrict__ wpe,
                             float* __restrict__ X)
{
    int i = blockIdx.x * 256 + threadIdx.x;
    if (i >= MM * EE) return;
    int m = i / EE;
    int e = i - m * EE;
    int tok = idx[m];
    X[i] = wte[(size_t)tok * EE + e] + wpe[(size_t)(m & (TT - 1)) * EE + e];
}

// ---------------- layernorm ----------------
__global__ void ln_kernel(const float* __restrict__ X,
                          const float* __restrict__ w,
                          const float* __restrict__ b,
                          float* __restrict__ O)
{
    int row = blockIdx.x;
    int t   = threadIdx.x;
    const float* xr = X + (size_t)row * EE;
    float v0 = xr[t], v1 = xr[t + 256], v2 = xr[t + 512];
    float s  = v0 + v1 + v2;
    float ss = v0 * v0 + v1 * v1 + v2 * v2;
    #pragma unroll
    for (int o = 16; o > 0; o >>= 1) {
        s  += __shfl_xor_sync(0xffffffffu, s, o);
        ss += __shfl_xor_sync(0xffffffffu, ss, o);
    }
    __shared__ float rs[8], rss[8];
    int wid = t >> 5, lid = t & 31;
    if (lid == 0) { rs[wid] = s; rss[wid] = ss; }
    __syncthreads();
    s = 0.f; ss = 0.f;
    #pragma unroll
    for (int i = 0; i < 8; i++) { s += rs[i]; ss += rss[i]; }
    float mean = s * (1.0f / EE);
    float var  = ss * (1.0f / EE) - mean * mean;
    float inv  = rsqrtf(var + LN_EPS);
    float* orow = O + (size_t)row * EE;
    orow[t]       = (v0 - mean) * inv * w[t]       + b[t];
    orow[t + 256] = (v1 - mean) * inv * w[t + 256] + b[t + 256];
    orow[t + 512] = (v2 - mean) * inv * w[t + 512] + b[t + 512];
}

// ---------------- causal attention (flash-style, 1 thread = 1 query row) -----------
__global__ __launch_bounds__(128)
void attn_kernel(const float* __restrict__ qkv, float* __restrict__ Y)
{
    int qt = blockIdx.x, h = blockIdx.y, b = blockIdx.z;
    int tid = threadIdx.x;
    int qi  = qt * 128 + tid;

    const float* base = qkv + (size_t)b * TT * E3;
    const float* qp   = base + (size_t)qi * E3 + h * HD;

    float q[HD], acc[HD];
    #pragma unroll
    for (int d = 0; d < HD; d += 4) {
        float4 u = *(const float4*)(qp + d);
        q[d] = u.x; q[d+1] = u.y; q[d+2] = u.z; q[d+3] = u.w;
        acc[d] = acc[d+1] = acc[d+2] = acc[d+3] = 0.f;
    }
    float mx = -INFINITY, l = 0.f;

    __shared__ __align__(16) float Ks[32][HD];
    __shared__ __align__(16) float Vs[32][HD];

    const float* kbase = base + EE     + h * HD;
    const float* vbase = base + 2 * EE + h * HD;
    int nkt = (qt + 1) * 4;

    for (int kt = 0; kt < nkt; kt++) {
        int j0 = kt * 32;
        __syncthreads();
        #pragma unroll
        for (int w = 0; w < 4; w++) {
            int p4 = tid + w * 128;
            int j  = p4 >> 4;
            int dc = (p4 & 15) * 4;
            *(float4*)&Ks[j][dc] = *(const float4*)(kbase + (size_t)(j0 + j) * E3 + dc);
            *(float4*)&Vs[j][dc] = *(const float4*)(vbase + (size_t)(j0 + j) * E3 + dc);
        }
        __syncthreads();

        #pragma unroll
        for (int half = 0; half < 2; half++) {
            int jb = half * 16;
            float s[16];
            #pragma unroll
            for (int j = 0; j < 16; j++) {
                float sum = 0.f;
                #pragma unroll
                for (int d = 0; d < HD; d += 4) {
                    float4 kv = *(const float4*)&Ks[jb + j][d];
                    sum += q[d] * kv.x + q[d+1] * kv.y + q[d+2] * kv.z + q[d+3] * kv.w;
                }
                s[j] = (j0 + jb + j <= qi) ? sum * 0.125f : -INFINITY;
            }
            float tmax = s[0];
            #pragma unroll
            for (int j = 1; j < 16; j++) tmax = fmaxf(tmax, s[j]);
            float nm   = fmaxf(mx, tmax);
            float corr = exp2f((mx - nm) * L2E);
            l *= corr;
            #pragma unroll
            for (int d = 0; d < HD; d++) acc[d] *= corr;
            #pragma unroll
            for (int j = 0; j < 16; j++) {
                float p = exp2f((s[j] - nm) * L2E);
                l += p;
                #pragma unroll
                for (int d = 0; d < HD; d += 4) {
                    float4 vv = *(const float4*)&Vs[jb + j][d];
                    acc[d]   += p * vv.x; acc[d+1] += p * vv.y;
                    acc[d+2] += p * vv.z; acc[d+3] += p * vv.w;
                }
            }
            mx = nm;
        }
    }
    float inv = 1.0f / l;
    float* yp = Y + (size_t)(b * TT + qi) * EE + h * HD;
    #pragma unroll
    for (int d = 0; d < HD; d += 4)
        *(float4*)(yp + d) = make_float4(acc[d] * inv, acc[d+1] * inv,
                                         acc[d+2] * inv, acc[d+3] * inv);
}

// ---------------- loss ----------------
__global__ void loss_row_kernel(const float* __restrict__ logits,
                                const int* __restrict__ tgt,
                                float* __restrict__ nll)
{
    int row = blockIdx.x;
    int t   = threadIdx.x;
    const float* Lr = logits + (size_t)row * VV;
    float mx = -INFINITY, s = 0.f;
    for (int j = t; j < VV; j += 256) {
        float x  = Lr[j];
        float nm = fmaxf(mx, x);
        s = s * exp2f((mx - nm) * L2E) + exp2f((x - nm) * L2E);
        mx = nm;
    }
    #pragma unroll
    for (int o = 16; o > 0; o >>= 1) {
        float om = __shfl_xor_sync(0xffffffffu, mx, o);
        float os = __shfl_xor_sync(0xffffffffu, s, o);
        float nm = fmaxf(mx, om);
        s = s * exp2f((mx - nm) * L2E) + os * exp2f((om - nm) * L2E);
        mx = nm;
    }
    __shared__ float sm[8], ssum[8];
    int wid = t >> 5, lid = t & 31;
    if (lid == 0) { sm[wid] = mx; ssum[wid] = s; }
    __syncthreads();
    if (t == 0) {
        float M = sm[0], S = ssum[0];
        #pragma unroll
        for (int i = 1; i < 8; i++) {
            float nm = fmaxf(M, sm[i]);
            S = S * exp2f((M - nm) * L2E) + ssum[i] * exp2f((sm[i] - nm) * L2E);
            M = nm;
        }
        int tg = tgt[row];
        nll[row] = (tg != -1) ? (M + logf(S)) - Lr[tg] : 0.f;
    }
}

__global__ void loss_final_kernel(const float* __restrict__ nll,
                                  const int* __restrict__ tgt,
                                  float* __restrict__ out)
{
    int t = threadIdx.x;
    float s = 0.f; int c = 0;
    for (int i = t; i < MM; i += 256) {
        if (tgt[i] != -1) { s += nll[i]; c++; }
    }
    #pragma unroll
    for (int o = 16; o > 0; o >>= 1) {
        s += __shfl_xor_sync(0xffffffffu, s, o);
        c += __shfl_xor_sync(0xffffffffu, c, o);
    }
    __shared__ float rs[8]; __shared__ int rc[8];
    int wid = t >> 5, lid = t & 31;
    if (lid == 0) { rs[wid] = s; rc[wid] = c; }
    __syncthreads();
    if (t == 0) {
        float S = 0.f; int C = 0;
        #pragma unroll
        for (int i = 0; i < 8; i++) { S += rs[i]; C += rc[i]; }
        out[0] = S / fmaxf((float)C, 1.f);
    }
}

// ---------------- host-side GEMM wrapper ----------------
static __nv_bfloat16 *h_asp = nullptr, *h_wsp = nullptr;

static void run_gemm(const float* A, const float* W, const float* bias,
                     const float* res, float* C, int M, int N, int K, int epi)
{
    int ta = (M * K) >> 2;
    int tw = (N * K) >> 2;
    split_a4<<<(ta + 255) / 256, 256>>>(A, h_asp, ta, K);
    split_w4<<<(tw + 255) / 256, 256>>>(W, h_wsp, tw, K);
    gemm_mma<<<dim3(M / 128, (N + 127) / 128), 256, GM_SMEM>>>(
        h_asp, h_wsp, bias, res, C, M, N, 3 * K, epi);
}

// ---------------- launcher ----------------
extern "C" void kernel_launch(void* const* d_in, const int* in_sizes, int n_in,
                              void* d_out, int out_size)
{
    const int*   idx        = (const int*)  d_in[0];
    const int*   tgt        = (const int*)  d_in[1];
    const float* wte        = (const float*)d_in[2];
    const float* wpe        = (const float*)d_in[3];
    const float* ln1_w      = (const float*)d_in[4];
    const float* ln1_b      = (const float*)d_in[5];
    const float* attn_w     = (const float*)d_in[6];
    const float* attn_b     = (const float*)d_in[7];
    const float* attnproj_w = (const float*)d_in[8];
    const float* attnproj_b = (const float*)d_in[9];
    const float* ln2_w      = (const float*)d_in[10];
    const float* ln2_b      = (const float*)d_in[11];
    const float* fc_w       = (const float*)d_in[12];
    const float* fc_b       = (const float*)d_in[13];
    const float* proj_w     = (const float*)d_in[14];
    const float* proj_b     = (const float*)d_in[15];
    const float* lnf_w      = (const float*)d_in[16];
    const float* lnf_b      = (const float*)d_in[17];

    float *x, *xn, *qkv, *y, *h1, *nll, *lfb;
    cudaGetSymbolAddress((void**)&x,   g_x);
    cudaGetSymbolAddress((void**)&xn,  g_xn);
    cudaGetSymbolAddress((void**)&qkv, g_qkv);
    cudaGetSymbolAddress((void**)&y,   g_y);
    cudaGetSymbolAddress((void**)&h1,  g_h1);
    cudaGetSymbolAddress((void**)&nll, g_nll);
    cudaGetSymbolAddress((void**)&lfb, g_logits_fb);
    cudaGetSymbolAddress((void**)&h_asp, g_asp);
    cudaGetSymbolAddress((void**)&h_wsp, g_wsp);

    cudaFuncSetAttribute(gemm_mma, cudaFuncAttributeMaxDynamicSharedMemorySize,
                         GM_SMEM);

    const long long BTV = (long long)MM * VV;
    float* logits = lfb;
    float* lossp  = nullptr;
    if ((long long)out_size == BTV + 1) { logits = (float*)d_out; lossp = (float*)d_out + BTV; }
    else if ((long long)out_size == BTV) { logits = (float*)d_out; }
    else { logits = lfb; lossp = (float*)d_out + (out_size - 1); }

    embed_kernel<<<(MM * EE + 255) / 256, 256>>>(idx, wte, wpe, x);

    for (int l = 0; l < LL; l++) {
        // --- attention block ---
        ln_kernel<<<MM, 256>>>(x, ln1_w + l * EE, ln1_b + l * EE, xn);
        run_gemm(xn, attn_w + (size_t)l * E3 * EE, attn_b + (size_t)l * E3,
                 nullptr, qkv, MM, E3, EE, 0);
        attn_kernel<<<dim3(TT / 128, HH, BB), 128>>>(qkv, y);
        run_gemm(y, attnproj_w + (size_t)l * EE * EE, attnproj_b + (size_t)l * EE,
                 x, x, MM, EE, EE, 2);
        // --- mlp block ---
        ln_kernel<<<MM, 256>>>(x, ln2_w + l * EE, ln2_b + l * EE, xn);
        run_gemm(xn, fc_w + (size_t)l * E4 * EE, fc_b + (size_t)l * E4,
                 nullptr, h1, MM, E4, EE, 3);
        run_gemm(h1, proj_w + (size_t)l * EE * E4, proj_b + (size_t)l * EE,
                 x, x, MM, EE, E4, 2);
    }

    // final LN + lm_head (tied wte)
    ln_kernel<<<MM, 256>>>(x, lnf_w, lnf_b, xn);
    run_gemm(xn, wte, nullptr, nullptr, logits, MM, VV, EE, 0);

    if (lossp) {
        loss_row_kernel<<<MM, 256>>>(logits, tgt, nll);
        loss_final_kernel<<<1, 256>>>(nll, tgt, lossp);
    }
}